// round 9
// baseline (speedup 1.0000x reference)
#include <cuda_runtime.h>

#define NH 16
#define HD 64
#define BB 2
#define SS 2048
#define DD 1024
#define ND (NH*HD)          // 1024
#define BHSD (BB*NH*SS*HD)  // 4,194,304 elems per tensor

// scratch as TF32 bit patterns: Q,K = [bh][s][d]; V = [bh][d][s] (transposed)
__device__ unsigned g_scr[3][BHSD];

// log2(e) and scaled mask constants
#define QSC 0.18033688011112042f          /* 0.125 * log2(e) */
#define CMSK 1.4426950408889634e10f       /* 1e10 * log2(e); ulp=1024 >> |scores| */

__device__ __forceinline__ unsigned f2tf(float x) {
    unsigned r; asm("cvt.rna.tf32.f32 %0, %1;" : "=r"(r) : "f"(x)); return r;
}
__device__ __forceinline__ float ex2(float x) {
    float r; asm("ex2.approx.f32 %0, %1;" : "=f"(r) : "f"(x)); return r;
}

__device__ __forceinline__ void mma8(float* c, const unsigned* a, const unsigned* b) {
    asm volatile(
        "mma.sync.aligned.m16n8k8.row.col.f32.tf32.tf32.f32 "
        "{%0,%1,%2,%3}, {%4,%5,%6,%7}, {%8,%9}, {%0,%1,%2,%3};\n"
        : "+f"(c[0]), "+f"(c[1]), "+f"(c[2]), "+f"(c[3])
        : "r"(a[0]), "r"(a[1]), "r"(a[2]), "r"(a[3]), "r"(b[0]), "r"(b[1]));
}

__device__ __forceinline__ void split2(float x, unsigned& h, unsigned& l) {
    unsigned hb = f2tf(x);
    float r = x - __uint_as_float(hb);
    h = hb; l = f2tf(r);
}

// ---------------------------------------------------------------------------
// Projections: A[4096,1024] @ W[1024,1024] -> g_scr[z] as TF32.
// 2-term split: (Ah + Al) @ tf32(W). BM=128,BN=128,BK=16, 8 warps.
// A tiles stored in permuted k-major layout [row][slot(k)], stride 20 words
//   slot(k) = (k&3)*4 + (k>>2)  =>  fragment loads are conflict-free LDS.128.
// LDG register prefetch pipeline. V epilogue stages through smem (coalesced).
// ---------------------------------------------------------------------------
__global__ __launch_bounds__(256, 2) void proj_kernel(
    const float* __restrict__ q, const float* __restrict__ k, const float* __restrict__ v,
    const float* __restrict__ Wq, const float* __restrict__ Wk, const float* __restrict__ Wv)
{
    __shared__ unsigned sbuf[8256];
    unsigned* AsH = sbuf;                               // [128][20] permuted
    unsigned* AsL = sbuf + 2560;                        // [128][20]
    unsigned (*WsH)[132] = (unsigned(*)[132])(sbuf + 5120);   // [16][132]

    const int which = blockIdx.z;
    const float* A = which == 0 ? q : (which == 1 ? k : v);
    const float* W = which == 0 ? Wq : (which == 1 ? Wk : Wv);

    const int tid = threadIdx.x;
    const int lane = tid & 31;
    const int w = tid >> 5;
    const int gid = lane >> 2, tig = lane & 3;
    const int wm = w >> 2, wn = w & 3;
    const int m0 = blockIdx.y * 128, n0 = blockIdx.x * 128;

    const int am = tid >> 1, ak = (tid & 1) * 8;
    const int wr = tid >> 4, wc = (tid & 15) * 8;

    const float* Ap = A + (size_t)(m0 + am) * DD + ak;
    const float* Wp = W + (size_t)wr * ND + n0 + wc;

    // precomputed permuted slots for this thread's 8 A columns (k = ak+j)
    int asl[8];
    #pragma unroll
    for (int j = 0; j < 8; j++) {
        int kk = ak + j;
        asl[j] = am * 20 + ((kk & 3) << 2) + (kk >> 2);
    }

    float C[4][4][4];
    #pragma unroll
    for (int i = 0; i < 4; i++)
        #pragma unroll
        for (int j = 0; j < 4; j++)
            #pragma unroll
            for (int e = 0; e < 4; e++) C[i][j][e] = 0.f;

    float4 ra0 = *(const float4*)(Ap);
    float4 ra1 = *(const float4*)(Ap + 4);
    float4 rw0 = *(const float4*)(Wp);
    float4 rw1 = *(const float4*)(Wp + 4);

    for (int k0 = 0; k0 < DD; k0 += 16) {
        __syncthreads();
        {
            float av[8] = {ra0.x, ra0.y, ra0.z, ra0.w, ra1.x, ra1.y, ra1.z, ra1.w};
            #pragma unroll
            for (int j = 0; j < 8; j++) {
                unsigned hb, lb;
                split2(av[j], hb, lb);
                AsH[asl[j]] = hb;
                AsL[asl[j]] = lb;
            }
            *(uint4*)&WsH[wr][wc]   = make_uint4(f2tf(rw0.x), f2tf(rw0.y), f2tf(rw0.z), f2tf(rw0.w));
            *(uint4*)&WsH[wr][wc+4] = make_uint4(f2tf(rw1.x), f2tf(rw1.y), f2tf(rw1.z), f2tf(rw1.w));
        }
        __syncthreads();

        if (k0 + 16 < DD) {
            ra0 = *(const float4*)(Ap + k0 + 16);
            ra1 = *(const float4*)(Ap + k0 + 20);
            rw0 = *(const float4*)(Wp + (size_t)(k0 + 16) * ND);
            rw1 = *(const float4*)(Wp + (size_t)(k0 + 16) * ND + 4);
        }

        #pragma unroll
        for (int ks = 0; ks < 2; ks++) {
            const int kk = ks * 8;
            unsigned bh[4][2];
            #pragma unroll
            for (int nf = 0; nf < 4; nf++) {
                int c = wn * 32 + nf * 8 + gid;
                bh[nf][0] = WsH[kk+tig][c];
                bh[nf][1] = WsH[kk+tig+4][c];
            }
            #pragma unroll
            for (int mf = 0; mf < 4; mf++) {
                int r = wm * 64 + mf * 16 + gid;
                uint4 h0 = *(const uint4*)&AsH[r * 20 + tig * 4];
                uint4 h1 = *(const uint4*)&AsH[(r + 8) * 20 + tig * 4];
                uint4 l0 = *(const uint4*)&AsL[r * 20 + tig * 4];
                uint4 l1 = *(const uint4*)&AsL[(r + 8) * 20 + tig * 4];
                unsigned ah[4], al[4];
                if (ks == 0) {
                    ah[0] = h0.x; ah[1] = h1.x; ah[2] = h0.y; ah[3] = h1.y;
                    al[0] = l0.x; al[1] = l1.x; al[2] = l0.y; al[3] = l1.y;
                } else {
                    ah[0] = h0.z; ah[1] = h1.z; ah[2] = h0.w; ah[3] = h1.w;
                    al[0] = l0.z; al[1] = l1.z; al[2] = l0.w; al[3] = l1.w;
                }
                #pragma unroll
                for (int nf = 0; nf < 4; nf++) {
                    mma8(C[mf][nf], al, bh[nf]);
                    mma8(C[mf][nf], ah, bh[nf]);
                }
            }
        }
    }

    unsigned* out = g_scr[which];
    if (which < 2) {
        #pragma unroll
        for (int mf = 0; mf < 4; mf++) {
            int R = m0 + wm * 64 + mf * 16 + gid;
            #pragma unroll
            for (int half = 0; half < 2; half++) {
                int Rr = R + half * 8;
                int bb = Rr >> 11;
                int s  = Rr & 2047;
                #pragma unroll
                for (int nf = 0; nf < 4; nf++) {
                    int Cc = n0 + wn * 32 + nf * 8 + tig * 2;
                    int hh = Cc >> 6, dd = Cc & 63;
                    size_t addr = ((size_t)(bb * NH + hh) * SS + s) * HD + dd;
                    uint2 vv;
                    vv.x = f2tf(C[mf][nf][half * 2 + 0]);
                    vv.y = f2tf(C[mf][nf][half * 2 + 1]);
                    *(uint2*)&out[addr] = vv;
                }
            }
        }
    } else {
        // V: [bh][d][s] via smem staging, coalesced stores
        float (*stg)[129] = (float(*)[129])(sbuf);
        #pragma unroll
        for (int ch = 0; ch < 2; ch++) {
            __syncthreads();
            if (wm == ch) {
                #pragma unroll
                for (int mf = 0; mf < 4; mf++)
                    #pragma unroll
                    for (int half = 0; half < 2; half++) {
                        int rr = mf * 16 + half * 8 + gid;
                        #pragma unroll
                        for (int nf = 0; nf < 4; nf++) {
                            int cc = wn * 32 + nf * 8 + tig * 2;
                            stg[rr][cc]     = C[mf][nf][half * 2 + 0];
                            stg[rr][cc + 1] = C[mf][nf][half * 2 + 1];
                        }
                    }
            }
            __syncthreads();
            const int base_s = m0 + ch * 64;
            const int bb = base_s >> 11;
            const int s_loc = base_s & 2047;
            #pragma unroll
            for (int cc = 0; cc < 16; cc++) {
                int c = w * 16 + cc;
                int hh = (n0 + c) >> 6, dd = (n0 + c) & 63;
                unsigned* dst = out + ((size_t)(bb * NH + hh) * HD + dd) * SS + s_loc;
                #pragma unroll
                for (int sg = 0; sg < 2; sg++) {
                    int s = sg * 32 + lane;
                    dst[s] = f2tf(stg[s][c]);
                }
            }
        }
    }
}

// ---------------------------------------------------------------------------
// Flash attention, TF32 mma. 128-q tile, 8 warps, 64-key tiles, 2 CTAs/SM.
// P stays in registers (QK C-frag == PV A-frag via permuted key columns).
// K/V DOUBLE-BUFFERED in smem: LDG(t+1) issued right after QK(t), covered by
// softmax+PV; STS into the other buffer; ONE __syncthreads per tile.
// Softmax in log2 domain (ex2.approx); log2e folded into Q scale & masks.
// ---------------------------------------------------------------------------
__global__ __launch_bounds__(256, 2) void attn_kernel(
    const int* __restrict__ v_mask, const int* __restrict__ q_mask,
    float* __restrict__ out)
{
    extern __shared__ unsigned smu[];
    unsigned* Qp = smu;                  // [128][68] permuted
    unsigned* KV = smu + 128 * 68;       // [2][ K:64*68 | V:64*68 ]
    float* kbb  = (float*)(KV + 4 * 64 * 68);   // [2][64]

    const int tid = threadIdx.x;
    const int lane = tid & 31;
    const int w = tid >> 5;
    const int gid = lane >> 2, tig = lane & 3;
    const int qt = gridDim.x - 1 - blockIdx.x;
    const int bh = blockIdx.y;
    const int b = bh >> 4, h = bh & 15;
    const int q0 = qt * 128;
    const int kt_hi = (q0 + 127) >> 6;
    const int NT = SS / 64;

    const unsigned* Qg = g_scr[0] + (size_t)bh * SS * HD;
    const unsigned* Kg = g_scr[1] + (size_t)bh * SS * HD;
    const unsigned* Vg = g_scr[2] + (size_t)bh * HD * SS;

    // load Q tile (permuted), folding in 0.125*log2e
    {
        const int lr = tid >> 1;
        const int half = tid & 1;
        #pragma unroll
        for (int j = 0; j < 8; j++) {
            int c0 = half * 32 + j * 4;
            uint4 vv = *(const uint4*)(Qg + (size_t)(q0 + lr) * HD + c0);
            int base = ((c0 >> 3) << 1) + ((c0 >> 2) & 1);
            Qp[lr * 68 + base]      = f2tf(__uint_as_float(vv.x) * QSC);
            Qp[lr * 68 + 16 + base] = f2tf(__uint_as_float(vv.y) * QSC);
            Qp[lr * 68 + 32 + base] = f2tf(__uint_as_float(vv.z) * QSC);
            Qp[lr * 68 + 48 + base] = f2tf(__uint_as_float(vv.w) * QSC);
        }
    }

    const float NEG_INF = __int_as_float(0xff800000);
    float m[2] = {NEG_INF, NEG_INF}, l[2] = {0.f, 0.f};
    float acc[8][4];
    #pragma unroll
    for (int of = 0; of < 8; of++)
        #pragma unroll
        for (int e = 0; e < 4; e++) acc[of][e] = 0.f;

    int deg = 0;
    const int rq = w * 16 + gid;
    const int llr = tid >> 2, lcq = tid & 3;
    const int koff = ((gid >> 1) + ((gid & 1) << 2)) * 68 + tig * 16;
    const int qoff  = rq * 68 + tig * 16;
    const int qoff2 = (rq + 8) * 68 + tig * 16;

    // per-thread STS target offsets (permuted layout)
    int stsb[4];
    #pragma unroll
    for (int j = 0; j < 4; j++) {
        int c0 = lcq * 16 + j * 4;
        stsb[j] = llr * 68 + ((c0 >> 3) << 1) + ((c0 >> 2) & 1);
    }

    uint4 rk[4], rv[4];
    float rkb = 0.f;

    // prologue: tile 0 -> buffer 0
    #pragma unroll
    for (int j = 0; j < 4; j++) {
        int c0 = lcq * 16 + j * 4;
        rk[j] = *(const uint4*)(Kg + (size_t)llr * HD + c0);
        rv[j] = *(const uint4*)(Vg + (size_t)llr * SS + c0);
    }
    if (tid < 64) rkb = v_mask[b * SS + tid] ? 0.f : -CMSK;
    {
        unsigned* Kb = KV;
        unsigned* Vb = KV + 64 * 68;
        #pragma unroll
        for (int j = 0; j < 4; j++) {
            Kb[stsb[j]]      = rk[j].x;  Kb[stsb[j] + 16] = rk[j].y;
            Kb[stsb[j] + 32] = rk[j].z;  Kb[stsb[j] + 48] = rk[j].w;
            Vb[stsb[j]]      = rv[j].x;  Vb[stsb[j] + 16] = rv[j].y;
            Vb[stsb[j] + 32] = rv[j].z;  Vb[stsb[j] + 48] = rv[j].w;
        }
        if (tid < 64) kbb[tid] = rkb;
    }
    __syncthreads();

    for (int kt = 0; kt < NT; kt++) {
        if (kt > kt_hi && !deg) break;
        const int k0 = kt * 64;
        const int cur = kt & 1, nxt = cur ^ 1;
        const unsigned* Kp = KV + cur * (2 * 64 * 68);
        const unsigned* Vp = Kp + 64 * 68;
        const float* kb = kbb + cur * 64;
        const bool pf = (kt + 1 < NT);

        // ---- QK: S(log2 units) = Qs @ K^T, key columns permuted ----
        float sc[8][4];
        #pragma unroll
        for (int nf = 0; nf < 8; nf++)
            #pragma unroll
            for (int e = 0; e < 4; e++) sc[nf][e] = 0.f;

        #pragma unroll
        for (int j = 0; j < 4; j++) {
            uint4 a0 = *(const uint4*)&Qp[qoff + j * 4];
            uint4 a1 = *(const uint4*)&Qp[qoff2 + j * 4];
            unsigned Ae[4] = {a0.x, a1.x, a0.y, a1.y};
            unsigned Ao[4] = {a0.z, a1.z, a0.w, a1.w};
            #pragma unroll
            for (int nf = 0; nf < 8; nf++) {
                uint4 bv = *(const uint4*)&Kp[nf * 544 + koff + j * 4];
                unsigned Be[2] = {bv.x, bv.y};
                unsigned Bo[2] = {bv.z, bv.w};
                mma8(sc[nf], Ae, Be);
                mma8(sc[nf], Ao, Bo);
            }
        }

        // ---- prefetch tile kt+1 (LDG overlapped by softmax + PV) ----
        if (pf) {
            const int nk0 = k0 + 64;
            #pragma unroll
            for (int j = 0; j < 4; j++) {
                int c0 = lcq * 16 + j * 4;
                rk[j] = *(const uint4*)(Kg + (size_t)(nk0 + llr) * HD + c0);
                rv[j] = *(const uint4*)(Vg + (size_t)llr * SS + nk0 + c0);
            }
            if (tid < 64) rkb = v_mask[b * SS + nk0 + tid] ? 0.f : -CMSK;
        }

        // ---- mask + online softmax; sc[nf][2i+jj] <-> key nf*8+tig+4*jj ----
        float kb0[8], kb1[8];
        #pragma unroll
        for (int nf = 0; nf < 8; nf++) {
            kb0[nf] = kb[nf * 8 + tig];
            kb1[nf] = kb[nf * 8 + tig + 4];
        }
        #pragma unroll
        for (int i = 0; i < 2; i++) {
            int qg = q0 + rq + 8 * i;
            float mx = NEG_INF;
            #pragma unroll
            for (int nf = 0; nf < 8; nf++) {
                float s0 = sc[nf][2 * i + 0] + kb0[nf];
                float s1 = sc[nf][2 * i + 1] + kb1[nf];
                if (k0 + nf * 8 + tig > qg)     s0 -= CMSK;
                if (k0 + nf * 8 + tig + 4 > qg) s1 -= CMSK;
                sc[nf][2 * i + 0] = s0;
                sc[nf][2 * i + 1] = s1;
                mx = fmaxf(mx, fmaxf(s0, s1));
            }
            mx = fmaxf(mx, __shfl_xor_sync(0xffffffffu, mx, 1));
            mx = fmaxf(mx, __shfl_xor_sync(0xffffffffu, mx, 2));
            float nm = fmaxf(m[i], mx);
            float rs = 0.f;
            #pragma unroll
            for (int nf = 0; nf < 8; nf++)
                #pragma unroll
                for (int jj = 0; jj < 2; jj++) {
                    float p = ex2(sc[nf][2 * i + jj] - nm);
                    rs += p;
                    sc[nf][2 * i + jj] = __uint_as_float(f2tf(p));
                }
            rs += __shfl_xor_sync(0xffffffffu, rs, 1);
            rs += __shfl_xor_sync(0xffffffffu, rs, 2);
            float alpha = ex2(m[i] - nm);
            l[i] = l[i] * alpha + rs;
            m[i] = nm;
            #pragma unroll
            for (int of = 0; of < 8; of++) {
                acc[of][2 * i + 0] *= alpha;
                acc[of][2 * i + 1] *= alpha;
            }
        }

        // ---- PV: O += P @ V, P straight from registers ----
        #pragma unroll
        for (int of = 0; of < 8; of++) {
            const unsigned* vb = &Vp[(of * 8 + gid) * 68 + tig * 16];
            uint4 ww[4];
            ww[0] = *(const uint4*)(vb);
            ww[1] = *(const uint4*)(vb + 4);
            ww[2] = *(const uint4*)(vb + 8);
            ww[3] = *(const uint4*)(vb + 12);
            #pragma unroll
            for (int nf = 0; nf < 8; nf++) {
                unsigned Af[4] = {__float_as_uint(sc[nf][0]), __float_as_uint(sc[nf][2]),
                                  __float_as_uint(sc[nf][1]), __float_as_uint(sc[nf][3])};
                unsigned Bf[2];
                if ((nf & 1) == 0) { Bf[0] = ((const unsigned*)&ww[nf >> 1])[0];
                                     Bf[1] = ((const unsigned*)&ww[nf >> 1])[1]; }
                else               { Bf[0] = ((const unsigned*)&ww[nf >> 1])[2];
                                     Bf[1] = ((const unsigned*)&ww[nf >> 1])[3]; }
                mma8(acc[of], Af, Bf);
            }
        }

        // ---- STS prefetched tile into the other buffer ----
        if (pf) {
            unsigned* Kb = KV + nxt * (2 * 64 * 68);
            unsigned* Vb = Kb + 64 * 68;
            #pragma unroll
            for (int j = 0; j < 4; j++) {
                Kb[stsb[j]]      = rk[j].x;  Kb[stsb[j] + 16] = rk[j].y;
                Kb[stsb[j] + 32] = rk[j].z;  Kb[stsb[j] + 48] = rk[j].w;
                Vb[stsb[j]]      = rv[j].x;  Vb[stsb[j] + 16] = rv[j].y;
                Vb[stsb[j] + 32] = rv[j].z;  Vb[stsb[j] + 48] = rv[j].w;
            }
            if (tid < 64) kbb[nxt * 64 + tid] = rkb;
        }

        // ---- single barrier per tile (doubles as degenerate-row vote) ----
        if (kt == kt_hi)
            deg = __syncthreads_or((m[0] < -1e10f) || (m[1] < -1e10f));
        else
            __syncthreads();
    }

    // epilogue
    #pragma unroll
    for (int i = 0; i < 2; i++) {
        int qg = q0 + rq + 8 * i;
        float qm = (float)q_mask[b * SS + qg];
        float f = qm / l[i];
        #pragma unroll
        for (int of = 0; of < 8; of++) {
            float2 o = make_float2(acc[of][2 * i + 0] * f, acc[of][2 * i + 1] * f);
            *(float2*)(out + ((size_t)b * SS + qg) * ND + h * HD + of * 8 + tig * 2) = o;
        }
    }
}

// ---------------------------------------------------------------------------
extern "C" void kernel_launch(void* const* d_in, const int* in_sizes, int n_in,
                              void* d_out, int out_size)
{
    const float* q  = (const float*)d_in[0];
    const float* k  = (const float*)d_in[1];
    const float* v  = (const float*)d_in[2];
    const int* vmask = (const int*)d_in[3];
    const int* qmask = (const int*)d_in[4];
    const float* Wq = (const float*)d_in[5];
    const float* Wk = (const float*)d_in[6];
    const float* Wv = (const float*)d_in[7];
    float* out = (float*)d_out;

    const int smem_attn = (128 * 68 + 4 * 64 * 68 + 2 * 64) * 4;   // 104,960 B
    cudaFuncSetAttribute(attn_kernel, cudaFuncAttributeMaxDynamicSharedMemorySize, smem_attn);

    dim3 gp(ND / 128, (BB * SS) / 128, 3);   // (8, 32, 3)
    proj_kernel<<<gp, 256>>>(q, k, v, Wq, Wk, Wv);

    dim3 ga(SS / 128, BB * NH);              // (16, 32)
    attn_kernel<<<ga, 256, smem_attn>>>(vmask, qmask, out);
}

// round 10
// speedup vs baseline: 1.5090x; 1.5090x over previous
#include <cuda_runtime.h>

#define NH 16
#define HD 64
#define BB 2
#define SS 2048
#define DD 1024
#define ND (NH*HD)          // 1024
#define BHSD (BB*NH*SS*HD)  // 4,194,304 elems per tensor

// scratch as TF32 bit patterns: Q,K = [bh][s][d]; V = [bh][d][s] (transposed)
__device__ unsigned g_scr[3][BHSD];

// log2(e) and scaled mask constants
#define QSC 0.18033688011112042f          /* 0.125 * log2(e) */
#define CMSK 1.4426950408889634e10f       /* 1e10 * log2(e); ulp=1024 >> |scores| */

__device__ __forceinline__ unsigned f2tf(float x) {
    unsigned r; asm("cvt.rna.tf32.f32 %0, %1;" : "=r"(r) : "f"(x)); return r;
}
__device__ __forceinline__ float ex2(float x) {
    float r; asm("ex2.approx.f32 %0, %1;" : "=f"(r) : "f"(x)); return r;
}

__device__ __forceinline__ void mma8(float* c, const unsigned* a, const unsigned* b) {
    asm volatile(
        "mma.sync.aligned.m16n8k8.row.col.f32.tf32.tf32.f32 "
        "{%0,%1,%2,%3}, {%4,%5,%6,%7}, {%8,%9}, {%0,%1,%2,%3};\n"
        : "+f"(c[0]), "+f"(c[1]), "+f"(c[2]), "+f"(c[3])
        : "r"(a[0]), "r"(a[1]), "r"(a[2]), "r"(a[3]), "r"(b[0]), "r"(b[1]));
}

__device__ __forceinline__ void split2(float x, unsigned& h, unsigned& l) {
    unsigned hb = f2tf(x);
    float r = x - __uint_as_float(hb);
    h = hb; l = f2tf(r);
}

// ---------------------------------------------------------------------------
// Projections (round-8 version, verbatim): A[4096,1024] @ W[1024,1024].
// 2-term split: (Ah + Al) @ tf32(W). BM=128,BN=128,BK=16, 8 warps.
// V (which==2) epilogue stages through smem for coalesced transposed stores.
// ---------------------------------------------------------------------------
__global__ __launch_bounds__(256) void proj_kernel(
    const float* __restrict__ q, const float* __restrict__ k, const float* __restrict__ v,
    const float* __restrict__ Wq, const float* __restrict__ Wk, const float* __restrict__ Wv)
{
    __shared__ unsigned sbuf[8256];
    unsigned (*AsH)[20]  = (unsigned(*)[20])(sbuf);
    unsigned (*AsL)[20]  = (unsigned(*)[20])(sbuf + 2560);
    unsigned (*WsH)[132] = (unsigned(*)[132])(sbuf + 5120);

    const int which = blockIdx.z;
    const float* A = which == 0 ? q : (which == 1 ? k : v);
    const float* W = which == 0 ? Wq : (which == 1 ? Wk : Wv);

    const int tid = threadIdx.x;
    const int lane = tid & 31;
    const int w = tid >> 5;
    const int gid = lane >> 2, tig = lane & 3;
    const int wm = w >> 2, wn = w & 3;
    const int m0 = blockIdx.y * 128, n0 = blockIdx.x * 128;

    const int am = tid >> 1, ak = (tid & 1) * 8;
    const int wr = tid >> 4, wc = (tid & 15) * 8;

    const float* Ap = A + (size_t)(m0 + am) * DD + ak;
    const float* Wp = W + (size_t)wr * ND + n0 + wc;

    float C[4][4][4];
    #pragma unroll
    for (int i = 0; i < 4; i++)
        #pragma unroll
        for (int j = 0; j < 4; j++)
            #pragma unroll
            for (int e = 0; e < 4; e++) C[i][j][e] = 0.f;

    for (int k0 = 0; k0 < DD; k0 += 16) {
        float4 a0 = *(const float4*)(Ap + k0);
        float4 a1 = *(const float4*)(Ap + k0 + 4);
        float4 w0 = *(const float4*)(Wp + (size_t)k0 * ND);
        float4 w1 = *(const float4*)(Wp + (size_t)k0 * ND + 4);
        __syncthreads();
        {
            unsigned h0,l0,h1,l1,h2,l2,h3,l3;
            split2(a0.x,h0,l0); split2(a0.y,h1,l1); split2(a0.z,h2,l2); split2(a0.w,h3,l3);
            *(uint4*)&AsH[am][ak]   = make_uint4(h0,h1,h2,h3);
            *(uint4*)&AsL[am][ak]   = make_uint4(l0,l1,l2,l3);
            split2(a1.x,h0,l0); split2(a1.y,h1,l1); split2(a1.z,h2,l2); split2(a1.w,h3,l3);
            *(uint4*)&AsH[am][ak+4] = make_uint4(h0,h1,h2,h3);
            *(uint4*)&AsL[am][ak+4] = make_uint4(l0,l1,l2,l3);
            *(uint4*)&WsH[wr][wc]   = make_uint4(f2tf(w0.x), f2tf(w0.y), f2tf(w0.z), f2tf(w0.w));
            *(uint4*)&WsH[wr][wc+4] = make_uint4(f2tf(w1.x), f2tf(w1.y), f2tf(w1.z), f2tf(w1.w));
        }
        __syncthreads();

        #pragma unroll
        for (int ks = 0; ks < 2; ks++) {
            const int kk = ks * 8;
            unsigned ah[4][4], al[4][4], bh[4][2];
            #pragma unroll
            for (int mf = 0; mf < 4; mf++) {
                int r = wm * 64 + mf * 16 + gid;
                ah[mf][0] = AsH[r][kk+tig];     al[mf][0] = AsL[r][kk+tig];
                ah[mf][1] = AsH[r+8][kk+tig];   al[mf][1] = AsL[r+8][kk+tig];
                ah[mf][2] = AsH[r][kk+tig+4];   al[mf][2] = AsL[r][kk+tig+4];
                ah[mf][3] = AsH[r+8][kk+tig+4]; al[mf][3] = AsL[r+8][kk+tig+4];
            }
            #pragma unroll
            for (int nf = 0; nf < 4; nf++) {
                int c = wn * 32 + nf * 8 + gid;
                bh[nf][0] = WsH[kk+tig][c];
                bh[nf][1] = WsH[kk+tig+4][c];
            }
            #pragma unroll
            for (int mf = 0; mf < 4; mf++)
                #pragma unroll
                for (int nf = 0; nf < 4; nf++) {
                    mma8(C[mf][nf], al[mf], bh[nf]);
                    mma8(C[mf][nf], ah[mf], bh[nf]);
                }
        }
    }

    unsigned* out = g_scr[which];
    if (which < 2) {
        #pragma unroll
        for (int mf = 0; mf < 4; mf++) {
            int R = m0 + wm * 64 + mf * 16 + gid;
            #pragma unroll
            for (int half = 0; half < 2; half++) {
                int Rr = R + half * 8;
                int bb = Rr >> 11;
                int s  = Rr & 2047;
                #pragma unroll
                for (int nf = 0; nf < 4; nf++) {
                    int Cc = n0 + wn * 32 + nf * 8 + tig * 2;
                    int hh = Cc >> 6, dd = Cc & 63;
                    size_t addr = ((size_t)(bb * NH + hh) * SS + s) * HD + dd;
                    uint2 vv;
                    vv.x = f2tf(C[mf][nf][half * 2 + 0]);
                    vv.y = f2tf(C[mf][nf][half * 2 + 1]);
                    *(uint2*)&out[addr] = vv;
                }
            }
        }
    } else {
        // V: [bh][d][s] via smem staging, coalesced stores
        float (*stg)[129] = (float(*)[129])(sbuf);
        #pragma unroll
        for (int ch = 0; ch < 2; ch++) {
            __syncthreads();
            if (wm == ch) {
                #pragma unroll
                for (int mf = 0; mf < 4; mf++)
                    #pragma unroll
                    for (int half = 0; half < 2; half++) {
                        int rr = mf * 16 + half * 8 + gid;
                        #pragma unroll
                        for (int nf = 0; nf < 4; nf++) {
                            int cc = wn * 32 + nf * 8 + tig * 2;
                            stg[rr][cc]     = C[mf][nf][half * 2 + 0];
                            stg[rr][cc + 1] = C[mf][nf][half * 2 + 1];
                        }
                    }
            }
            __syncthreads();
            const int base_s = m0 + ch * 64;
            const int bb = base_s >> 11;
            const int s_loc = base_s & 2047;
            #pragma unroll
            for (int cc = 0; cc < 16; cc++) {
                int c = w * 16 + cc;
                int hh = (n0 + c) >> 6, dd = (n0 + c) & 63;
                unsigned* dst = out + ((size_t)(bb * NH + hh) * HD + dd) * SS + s_loc;
                #pragma unroll
                for (int sg = 0; sg < 2; sg++) {
                    int s = sg * 32 + lane;
                    dst[s] = f2tf(stg[s][c]);
                }
            }
        }
    }
}

// ---------------------------------------------------------------------------
// Flash attention, TF32 mma. 128-q tile, 4 WARPS x 32 rows (two m-frags per
// warp: K and V fragments are loaded ONCE and feed both m-frags => ~44% less
// smem read traffic per unit work). 64-key tiles, 2 CTAs/SM.
// P stays in registers (QK C-frag == PV A-frag via permuted key columns).
// K/V double-buffered; one __syncthreads per tile. ex2 softmax in log2 units.
// ---------------------------------------------------------------------------
__global__ __launch_bounds__(128, 2) void attn_kernel(
    const int* __restrict__ v_mask, const int* __restrict__ q_mask,
    float* __restrict__ out)
{
    extern __shared__ unsigned smu[];
    unsigned* Qp = smu;                  // [128][68] permuted
    unsigned* KV = smu + 128 * 68;       // [2][ K:64*68 | V:64*68 ]
    float* kbb  = (float*)(KV + 4 * 64 * 68);   // [2][64]

    const int tid = threadIdx.x;
    const int lane = tid & 31;
    const int w = tid >> 5;              // 0..3
    const int gid = lane >> 2, tig = lane & 3;
    const int qt = gridDim.x - 1 - blockIdx.x;
    const int bh = blockIdx.y;
    const int b = bh >> 4, h = bh & 15;
    const int q0 = qt * 128;
    const int kt_hi = (q0 + 127) >> 6;
    const int NT = SS / 64;

    const unsigned* Qg = g_scr[0] + (size_t)bh * SS * HD;
    const unsigned* Kg = g_scr[1] + (size_t)bh * SS * HD;
    const unsigned* Vg = g_scr[2] + (size_t)bh * HD * SS;

    // load Q tile (permuted), folding in 0.125*log2e; 1 row per thread
    {
        const int lr = tid;
        #pragma unroll
        for (int j = 0; j < 16; j++) {
            int c0 = j * 4;
            uint4 vv = *(const uint4*)(Qg + (size_t)(q0 + lr) * HD + c0);
            int base = ((c0 >> 3) << 1) + ((c0 >> 2) & 1);
            Qp[lr * 68 + base]      = f2tf(__uint_as_float(vv.x) * QSC);
            Qp[lr * 68 + 16 + base] = f2tf(__uint_as_float(vv.y) * QSC);
            Qp[lr * 68 + 32 + base] = f2tf(__uint_as_float(vv.z) * QSC);
            Qp[lr * 68 + 48 + base] = f2tf(__uint_as_float(vv.w) * QSC);
        }
    }

    const float NEG_INF = __int_as_float(0xff800000);
    float m[2][2] = {{NEG_INF, NEG_INF}, {NEG_INF, NEG_INF}};
    float l[2][2] = {{0.f, 0.f}, {0.f, 0.f}};
    float acc[2][8][4];
    #pragma unroll
    for (int mf = 0; mf < 2; mf++)
        #pragma unroll
        for (int of = 0; of < 8; of++)
            #pragma unroll
            for (int e = 0; e < 4; e++) acc[mf][of][e] = 0.f;

    int deg = 0;
    const int rq = w * 32 + gid;         // m-frag0 base row; m-frag1 at +16
    // loader mapping: 128 threads cover 64 rows x 2 half-rows
    const int llr = tid >> 1;            // K/V row 0..63
    const int lgh = (tid & 1) * 2;       // group base: 0 or 2 (two 16-word groups)
    const int koff = ((gid >> 1) + ((gid & 1) << 2)) * 68 + tig * 16;
    const int qoff0 = rq * 68 + tig * 16;
    const int qoff1 = (rq + 8) * 68 + tig * 16;
    const int qoff2 = (rq + 16) * 68 + tig * 16;
    const int qoff3 = (rq + 24) * 68 + tig * 16;

    // per-thread STS target offsets (permuted layout): 8 uint4 per tensor
    int stsb[2][4];
    #pragma unroll
    for (int g = 0; g < 2; g++)
        #pragma unroll
        for (int j = 0; j < 4; j++) {
            int c0 = (lgh + g) * 16 + j * 4;
            stsb[g][j] = llr * 68 + ((c0 >> 3) << 1) + ((c0 >> 2) & 1);
        }

    uint4 rk[2][4], rv[2][4];
    float rkb = 0.f;

    // prologue: tile 0 -> buffer 0
    #pragma unroll
    for (int g = 0; g < 2; g++)
        #pragma unroll
        for (int j = 0; j < 4; j++) {
            int c0 = (lgh + g) * 16 + j * 4;
            rk[g][j] = *(const uint4*)(Kg + (size_t)llr * HD + c0);
            rv[g][j] = *(const uint4*)(Vg + (size_t)llr * SS + c0);
        }
    if (tid < 64) rkb = v_mask[b * SS + tid] ? 0.f : -CMSK;
    {
        unsigned* Kb = KV;
        unsigned* Vb = KV + 64 * 68;
        #pragma unroll
        for (int g = 0; g < 2; g++)
            #pragma unroll
            for (int j = 0; j < 4; j++) {
                Kb[stsb[g][j]]      = rk[g][j].x;  Kb[stsb[g][j] + 16] = rk[g][j].y;
                Kb[stsb[g][j] + 32] = rk[g][j].z;  Kb[stsb[g][j] + 48] = rk[g][j].w;
                Vb[stsb[g][j]]      = rv[g][j].x;  Vb[stsb[g][j] + 16] = rv[g][j].y;
                Vb[stsb[g][j] + 32] = rv[g][j].z;  Vb[stsb[g][j] + 48] = rv[g][j].w;
            }
        if (tid < 64) kbb[tid] = rkb;
    }
    __syncthreads();

    for (int kt = 0; kt < NT; kt++) {
        if (kt > kt_hi && !deg) break;
        const int k0 = kt * 64;
        const int cur = kt & 1, nxt = cur ^ 1;
        const unsigned* Kp = KV + cur * (2 * 64 * 68);
        const unsigned* Vp = Kp + 64 * 68;
        const float* kb = kbb + cur * 64;
        const bool pf = (kt + 1 < NT);

        // ---- QK: both m-frags share each K fragment load ----
        float sc[2][8][4];
        #pragma unroll
        for (int mf = 0; mf < 2; mf++)
            #pragma unroll
            for (int nf = 0; nf < 8; nf++)
                #pragma unroll
                for (int e = 0; e < 4; e++) sc[mf][nf][e] = 0.f;

        #pragma unroll
        for (int j = 0; j < 4; j++) {
            uint4 a0 = *(const uint4*)&Qp[qoff0 + j * 4];
            uint4 a1 = *(const uint4*)&Qp[qoff1 + j * 4];
            uint4 a2 = *(const uint4*)&Qp[qoff2 + j * 4];
            uint4 a3 = *(const uint4*)&Qp[qoff3 + j * 4];
            unsigned Ae0[4] = {a0.x, a1.x, a0.y, a1.y};
            unsigned Ao0[4] = {a0.z, a1.z, a0.w, a1.w};
            unsigned Ae1[4] = {a2.x, a3.x, a2.y, a3.y};
            unsigned Ao1[4] = {a2.z, a3.z, a2.w, a3.w};
            #pragma unroll
            for (int nf = 0; nf < 8; nf++) {
                uint4 bv = *(const uint4*)&Kp[nf * 544 + koff + j * 4];
                unsigned Be[2] = {bv.x, bv.y};
                unsigned Bo[2] = {bv.z, bv.w};
                mma8(sc[0][nf], Ae0, Be);
                mma8(sc[0][nf], Ao0, Bo);
                mma8(sc[1][nf], Ae1, Be);
                mma8(sc[1][nf], Ao1, Bo);
            }
        }

        // ---- prefetch tile kt+1 (LDG overlapped by softmax + PV) ----
        if (pf) {
            const int nk0 = k0 + 64;
            #pragma unroll
            for (int g = 0; g < 2; g++)
                #pragma unroll
                for (int j = 0; j < 4; j++) {
                    int c0 = (lgh + g) * 16 + j * 4;
                    rk[g][j] = *(const uint4*)(Kg + (size_t)(nk0 + llr) * HD + c0);
                    rv[g][j] = *(const uint4*)(Vg + (size_t)llr * SS + nk0 + c0);
                }
            if (tid < 64) rkb = v_mask[b * SS + nk0 + tid] ? 0.f : -CMSK;
        }

        // ---- mask + online softmax; sc[mf][nf][2i+jj] <-> key nf*8+tig+4*jj ----
        float kb0[8], kb1[8];
        #pragma unroll
        for (int nf = 0; nf < 8; nf++) {
            kb0[nf] = kb[nf * 8 + tig];
            kb1[nf] = kb[nf * 8 + tig + 4];
        }
        #pragma unroll
        for (int mf = 0; mf < 2; mf++)
            #pragma unroll
            for (int i = 0; i < 2; i++) {
                int qg = q0 + rq + mf * 16 + 8 * i;
                float mx = NEG_INF;
                #pragma unroll
                for (int nf = 0; nf < 8; nf++) {
                    float s0 = sc[mf][nf][2 * i + 0] + kb0[nf];
                    float s1 = sc[mf][nf][2 * i + 1] + kb1[nf];
                    if (k0 + nf * 8 + tig > qg)     s0 -= CMSK;
                    if (k0 + nf * 8 + tig + 4 > qg) s1 -= CMSK;
                    sc[mf][nf][2 * i + 0] = s0;
                    sc[mf][nf][2 * i + 1] = s1;
                    mx = fmaxf(mx, fmaxf(s0, s1));
                }
                mx = fmaxf(mx, __shfl_xor_sync(0xffffffffu, mx, 1));
                mx = fmaxf(mx, __shfl_xor_sync(0xffffffffu, mx, 2));
                float nm = fmaxf(m[mf][i], mx);
                float rs = 0.f;
                #pragma unroll
                for (int nf = 0; nf < 8; nf++)
                    #pragma unroll
                    for (int jj = 0; jj < 2; jj++) {
                        float p = ex2(sc[mf][nf][2 * i + jj] - nm);
                        rs += p;
                        sc[mf][nf][2 * i + jj] = __uint_as_float(f2tf(p));
                    }
                rs += __shfl_xor_sync(0xffffffffu, rs, 1);
                rs += __shfl_xor_sync(0xffffffffu, rs, 2);
                float alpha = ex2(m[mf][i] - nm);
                l[mf][i] = l[mf][i] * alpha + rs;
                m[mf][i] = nm;
                #pragma unroll
                for (int of = 0; of < 8; of++) {
                    acc[mf][of][2 * i + 0] *= alpha;
                    acc[mf][of][2 * i + 1] *= alpha;
                }
            }

        // ---- PV: both m-frags share each V fragment load ----
        #pragma unroll
        for (int of = 0; of < 8; of++) {
            const unsigned* vb = &Vp[(of * 8 + gid) * 68 + tig * 16];
            uint4 ww[4];
            ww[0] = *(const uint4*)(vb);
            ww[1] = *(const uint4*)(vb + 4);
            ww[2] = *(const uint4*)(vb + 8);
            ww[3] = *(const uint4*)(vb + 12);
            #pragma unroll
            for (int nf = 0; nf < 8; nf++) {
                unsigned Bf[2];
                if ((nf & 1) == 0) { Bf[0] = ((const unsigned*)&ww[nf >> 1])[0];
                                     Bf[1] = ((const unsigned*)&ww[nf >> 1])[1]; }
                else               { Bf[0] = ((const unsigned*)&ww[nf >> 1])[2];
                                     Bf[1] = ((const unsigned*)&ww[nf >> 1])[3]; }
                #pragma unroll
                for (int mf = 0; mf < 2; mf++) {
                    unsigned Af[4] = {__float_as_uint(sc[mf][nf][0]), __float_as_uint(sc[mf][nf][2]),
                                      __float_as_uint(sc[mf][nf][1]), __float_as_uint(sc[mf][nf][3])};
                    mma8(acc[mf][of], Af, Bf);
                }
            }
        }

        // ---- STS prefetched tile into the other buffer ----
        if (pf) {
            unsigned* Kb = KV + nxt * (2 * 64 * 68);
            unsigned* Vb = Kb + 64 * 68;
            #pragma unroll
            for (int g = 0; g < 2; g++)
                #pragma unroll
                for (int j = 0; j < 4; j++) {
                    Kb[stsb[g][j]]      = rk[g][j].x;  Kb[stsb[g][j] + 16] = rk[g][j].y;
                    Kb[stsb[g][j] + 32] = rk[g][j].z;  Kb[stsb[g][j] + 48] = rk[g][j].w;
                    Vb[stsb[g][j]]      = rv[g][j].x;  Vb[stsb[g][j] + 16] = rv[g][j].y;
                    Vb[stsb[g][j] + 32] = rv[g][j].z;  Vb[stsb[g][j] + 48] = rv[g][j].w;
                }
            if (tid < 64) kbb[nxt * 64 + tid] = rkb;
        }

        // ---- single barrier per tile (doubles as degenerate-row vote) ----
        if (kt == kt_hi)
            deg = __syncthreads_or((m[0][0] < -1e10f) || (m[0][1] < -1e10f) ||
                                   (m[1][0] < -1e10f) || (m[1][1] < -1e10f));
        else
            __syncthreads();
    }

    // epilogue
    #pragma unroll
    for (int mf = 0; mf < 2; mf++)
        #pragma unroll
        for (int i = 0; i < 2; i++) {
            int qg = q0 + rq + mf * 16 + 8 * i;
            float qm = (float)q_mask[b * SS + qg];
            float f = qm / l[mf][i];
            #pragma unroll
            for (int of = 0; of < 8; of++) {
                float2 o = make_float2(acc[mf][of][2 * i + 0] * f, acc[mf][of][2 * i + 1] * f);
                *(float2*)(out + ((size_t)b * SS + qg) * ND + h * HD + of * 8 + tig * 2) = o;
            }
        }
}

// ---------------------------------------------------------------------------
extern "C" void kernel_launch(void* const* d_in, const int* in_sizes, int n_in,
                              void* d_out, int out_size)
{
    const float* q  = (const float*)d_in[0];
    const float* k  = (const float*)d_in[1];
    const float* v  = (const float*)d_in[2];
    const int* vmask = (const int*)d_in[3];
    const int* qmask = (const int*)d_in[4];
    const float* Wq = (const float*)d_in[5];
    const float* Wk = (const float*)d_in[6];
    const float* Wv = (const float*)d_in[7];
    float* out = (float*)d_out;

    const int smem_attn = (128 * 68 + 4 * 64 * 68 + 2 * 64) * 4;   // 104,960 B
    cudaFuncSetAttribute(attn_kernel, cudaFuncAttributeMaxDynamicSharedMemorySize, smem_attn);

    dim3 gp(ND / 128, (BB * SS) / 128, 3);   // (8, 32, 3)
    proj_kernel<<<gp, 256>>>(q, k, v, Wq, Wk, Wv);

    dim3 ga(SS / 128, BB * NH);              // (16, 32)
    attn_kernel<<<ga, 128, smem_attn>>>(vmask, qmask, out);
}

// round 11
// speedup vs baseline: 1.5312x; 1.0147x over previous
#include <cuda_runtime.h>

#define NH 16
#define HD 64
#define BB 2
#define SS 2048
#define DD 1024
#define ND (NH*HD)          // 1024
#define BHSD (BB*NH*SS*HD)  // 4,194,304 elems per tensor

// scratch as TF32 bit patterns: Q,K = [bh][s][d]; V = [bh][d][s] (transposed)
__device__ unsigned g_scr[3][BHSD];

// log2(e) and scaled mask constants
#define QSC 0.18033688011112042f          /* 0.125 * log2(e) */
#define CMSK 1.4426950408889634e10f       /* 1e10 * log2(e); ulp=1024 >> |scores| */

__device__ __forceinline__ unsigned f2tf(float x) {
    unsigned r; asm("cvt.rna.tf32.f32 %0, %1;" : "=r"(r) : "f"(x)); return r;
}
__device__ __forceinline__ float ex2(float x) {
    float r; asm("ex2.approx.f32 %0, %1;" : "=f"(r) : "f"(x)); return r;
}

__device__ __forceinline__ void mma8(float* c, const unsigned* a, const unsigned* b) {
    asm volatile(
        "mma.sync.aligned.m16n8k8.row.col.f32.tf32.tf32.f32 "
        "{%0,%1,%2,%3}, {%4,%5,%6,%7}, {%8,%9}, {%0,%1,%2,%3};\n"
        : "+f"(c[0]), "+f"(c[1]), "+f"(c[2]), "+f"(c[3])
        : "r"(a[0]), "r"(a[1]), "r"(a[2]), "r"(a[3]), "r"(b[0]), "r"(b[1]));
}

__device__ __forceinline__ void split2(float x, unsigned& h, unsigned& l) {
    unsigned hb = f2tf(x);
    float r = x - __uint_as_float(hb);
    h = hb; l = f2tf(r);
}

// ---------------------------------------------------------------------------
// Projections: A[4096,1024] @ W[1024,1024] -> g_scr[z] as TF32.
// 2-term split: (Ah + Al) @ tf32(W). BM=128,BN=128,BK=16.
// 4 WARPS, warp tile 64x64 (warp grid 2x2): A fragments feed 8 n-frags
// instead of 4 => 0.75 LDS per mma (was 1.25). No LDG prefetch.
// Per-element accumulation order identical to round-8 => bit-identical output.
// V (which==2) epilogue stages through smem for coalesced transposed stores.
// ---------------------------------------------------------------------------
__global__ __launch_bounds__(128) void proj_kernel(
    const float* __restrict__ q, const float* __restrict__ k, const float* __restrict__ v,
    const float* __restrict__ Wq, const float* __restrict__ Wk, const float* __restrict__ Wv)
{
    __shared__ unsigned sbuf[8256];
    unsigned (*AsH)[20]  = (unsigned(*)[20])(sbuf);          // [128][20]
    unsigned (*AsL)[20]  = (unsigned(*)[20])(sbuf + 2560);   // [128][20]
    unsigned (*WsH)[132] = (unsigned(*)[132])(sbuf + 5120);  // [16][132]

    const int which = blockIdx.z;
    const float* A = which == 0 ? q : (which == 1 ? k : v);
    const float* W = which == 0 ? Wq : (which == 1 ? Wk : Wv);

    const int tid = threadIdx.x;
    const int lane = tid & 31;
    const int w = tid >> 5;              // 0..3
    const int gid = lane >> 2, tig = lane & 3;
    const int wm = w >> 1, wn = w & 1;   // 2x2 warp grid, warp tile 64x64
    const int m0 = blockIdx.y * 128, n0 = blockIdx.x * 128;

    const int am = tid;                  // A row 0..127, 16 k per thread
    const int wr = tid >> 4;             // W rows wr and wr+8 (0..7)
    const int wc = (tid & 15) * 8;       // 8 cols per row

    const float* Ap = A + (size_t)(m0 + am) * DD;
    const float* Wp = W + (size_t)wr * ND + n0 + wc;

    float C[4][8][4];
    #pragma unroll
    for (int i = 0; i < 4; i++)
        #pragma unroll
        for (int j = 0; j < 8; j++)
            #pragma unroll
            for (int e = 0; e < 4; e++) C[i][j][e] = 0.f;

    for (int k0 = 0; k0 < DD; k0 += 16) {
        float4 a0 = *(const float4*)(Ap + k0);
        float4 a1 = *(const float4*)(Ap + k0 + 4);
        float4 a2 = *(const float4*)(Ap + k0 + 8);
        float4 a3 = *(const float4*)(Ap + k0 + 12);
        float4 w0 = *(const float4*)(Wp + (size_t)k0 * ND);
        float4 w1 = *(const float4*)(Wp + (size_t)k0 * ND + 4);
        float4 w2 = *(const float4*)(Wp + (size_t)(k0 + 8) * ND);
        float4 w3 = *(const float4*)(Wp + (size_t)(k0 + 8) * ND + 4);
        __syncthreads();
        {
            unsigned h0,l0,h1,l1,h2,l2,h3,l3;
            split2(a0.x,h0,l0); split2(a0.y,h1,l1); split2(a0.z,h2,l2); split2(a0.w,h3,l3);
            *(uint4*)&AsH[am][0]  = make_uint4(h0,h1,h2,h3);
            *(uint4*)&AsL[am][0]  = make_uint4(l0,l1,l2,l3);
            split2(a1.x,h0,l0); split2(a1.y,h1,l1); split2(a1.z,h2,l2); split2(a1.w,h3,l3);
            *(uint4*)&AsH[am][4]  = make_uint4(h0,h1,h2,h3);
            *(uint4*)&AsL[am][4]  = make_uint4(l0,l1,l2,l3);
            split2(a2.x,h0,l0); split2(a2.y,h1,l1); split2(a2.z,h2,l2); split2(a2.w,h3,l3);
            *(uint4*)&AsH[am][8]  = make_uint4(h0,h1,h2,h3);
            *(uint4*)&AsL[am][8]  = make_uint4(l0,l1,l2,l3);
            split2(a3.x,h0,l0); split2(a3.y,h1,l1); split2(a3.z,h2,l2); split2(a3.w,h3,l3);
            *(uint4*)&AsH[am][12] = make_uint4(h0,h1,h2,h3);
            *(uint4*)&AsL[am][12] = make_uint4(l0,l1,l2,l3);
            *(uint4*)&WsH[wr][wc]       = make_uint4(f2tf(w0.x), f2tf(w0.y), f2tf(w0.z), f2tf(w0.w));
            *(uint4*)&WsH[wr][wc+4]     = make_uint4(f2tf(w1.x), f2tf(w1.y), f2tf(w1.z), f2tf(w1.w));
            *(uint4*)&WsH[wr+8][wc]     = make_uint4(f2tf(w2.x), f2tf(w2.y), f2tf(w2.z), f2tf(w2.w));
            *(uint4*)&WsH[wr+8][wc+4]   = make_uint4(f2tf(w3.x), f2tf(w3.y), f2tf(w3.z), f2tf(w3.w));
        }
        __syncthreads();

        #pragma unroll
        for (int ks = 0; ks < 2; ks++) {
            const int kk = ks * 8;
            unsigned ah[4][4], al[4][4], bh[8][2];
            #pragma unroll
            for (int mf = 0; mf < 4; mf++) {
                int r = wm * 64 + mf * 16 + gid;
                ah[mf][0] = AsH[r][kk+tig];     al[mf][0] = AsL[r][kk+tig];
                ah[mf][1] = AsH[r+8][kk+tig];   al[mf][1] = AsL[r+8][kk+tig];
                ah[mf][2] = AsH[r][kk+tig+4];   al[mf][2] = AsL[r][kk+tig+4];
                ah[mf][3] = AsH[r+8][kk+tig+4]; al[mf][3] = AsL[r+8][kk+tig+4];
            }
            #pragma unroll
            for (int nf = 0; nf < 8; nf++) {
                int c = wn * 64 + nf * 8 + gid;
                bh[nf][0] = WsH[kk+tig][c];
                bh[nf][1] = WsH[kk+tig+4][c];
            }
            #pragma unroll
            for (int mf = 0; mf < 4; mf++)
                #pragma unroll
                for (int nf = 0; nf < 8; nf++) {
                    mma8(C[mf][nf], al[mf], bh[nf]);
                    mma8(C[mf][nf], ah[mf], bh[nf]);
                }
        }
    }

    unsigned* out = g_scr[which];
    if (which < 2) {
        #pragma unroll
        for (int mf = 0; mf < 4; mf++) {
            int R = m0 + wm * 64 + mf * 16 + gid;
            #pragma unroll
            for (int half = 0; half < 2; half++) {
                int Rr = R + half * 8;
                int bb = Rr >> 11;
                int s  = Rr & 2047;
                #pragma unroll
                for (int nf = 0; nf < 8; nf++) {
                    int Cc = n0 + wn * 64 + nf * 8 + tig * 2;
                    int hh = Cc >> 6, dd = Cc & 63;
                    size_t addr = ((size_t)(bb * NH + hh) * SS + s) * HD + dd;
                    uint2 vv;
                    vv.x = f2tf(C[mf][nf][half * 2 + 0]);
                    vv.y = f2tf(C[mf][nf][half * 2 + 1]);
                    *(uint2*)&out[addr] = vv;
                }
            }
        }
    } else {
        // V: [bh][d][s] via smem staging, coalesced stores
        float (*stg)[129] = (float(*)[129])(sbuf);
        #pragma unroll
        for (int ch = 0; ch < 2; ch++) {
            __syncthreads();
            if (wm == ch) {
                #pragma unroll
                for (int mf = 0; mf < 4; mf++)
                    #pragma unroll
                    for (int half = 0; half < 2; half++) {
                        int rr = mf * 16 + half * 8 + gid;
                        #pragma unroll
                        for (int nf = 0; nf < 8; nf++) {
                            int cc = wn * 64 + nf * 8 + tig * 2;
                            stg[rr][cc]     = C[mf][nf][half * 2 + 0];
                            stg[rr][cc + 1] = C[mf][nf][half * 2 + 1];
                        }
                    }
            }
            __syncthreads();
            const int base_s = m0 + ch * 64;
            const int bb = base_s >> 11;
            const int s_loc = base_s & 2047;
            #pragma unroll
            for (int cc = 0; cc < 32; cc++) {
                int c = w * 32 + cc;
                int hh = (n0 + c) >> 6, dd = (n0 + c) & 63;
                unsigned* dst = out + ((size_t)(bb * NH + hh) * HD + dd) * SS + s_loc;
                #pragma unroll
                for (int sg = 0; sg < 2; sg++) {
                    int s = sg * 32 + lane;
                    dst[s] = f2tf(stg[s][c]);
                }
            }
        }
    }
}

// ---------------------------------------------------------------------------
// Flash attention (round-10, unchanged). TF32 mma. 128-q tile, 4 warps x
// 32 rows (two m-frags share K/V fragment loads). 64-key tiles, 2 CTAs/SM.
// P stays in registers; K/V double-buffered; one __syncthreads per tile.
// ---------------------------------------------------------------------------
__global__ __launch_bounds__(128, 2) void attn_kernel(
    const int* __restrict__ v_mask, const int* __restrict__ q_mask,
    float* __restrict__ out)
{
    extern __shared__ unsigned smu[];
    unsigned* Qp = smu;                  // [128][68] permuted
    unsigned* KV = smu + 128 * 68;       // [2][ K:64*68 | V:64*68 ]
    float* kbb  = (float*)(KV + 4 * 64 * 68);   // [2][64]

    const int tid = threadIdx.x;
    const int lane = tid & 31;
    const int w = tid >> 5;              // 0..3
    const int gid = lane >> 2, tig = lane & 3;
    const int qt = gridDim.x - 1 - blockIdx.x;
    const int bh = blockIdx.y;
    const int b = bh >> 4, h = bh & 15;
    const int q0 = qt * 128;
    const int kt_hi = (q0 + 127) >> 6;
    const int NT = SS / 64;

    const unsigned* Qg = g_scr[0] + (size_t)bh * SS * HD;
    const unsigned* Kg = g_scr[1] + (size_t)bh * SS * HD;
    const unsigned* Vg = g_scr[2] + (size_t)bh * HD * SS;

    // load Q tile (permuted), folding in 0.125*log2e; 1 row per thread
    {
        const int lr = tid;
        #pragma unroll
        for (int j = 0; j < 16; j++) {
            int c0 = j * 4;
            uint4 vv = *(const uint4*)(Qg + (size_t)(q0 + lr) * HD + c0);
            int base = ((c0 >> 3) << 1) + ((c0 >> 2) & 1);
            Qp[lr * 68 + base]      = f2tf(__uint_as_float(vv.x) * QSC);
            Qp[lr * 68 + 16 + base] = f2tf(__uint_as_float(vv.y) * QSC);
            Qp[lr * 68 + 32 + base] = f2tf(__uint_as_float(vv.z) * QSC);
            Qp[lr * 68 + 48 + base] = f2tf(__uint_as_float(vv.w) * QSC);
        }
    }

    const float NEG_INF = __int_as_float(0xff800000);
    float m[2][2] = {{NEG_INF, NEG_INF}, {NEG_INF, NEG_INF}};
    float l[2][2] = {{0.f, 0.f}, {0.f, 0.f}};
    float acc[2][8][4];
    #pragma unroll
    for (int mf = 0; mf < 2; mf++)
        #pragma unroll
        for (int of = 0; of < 8; of++)
            #pragma unroll
            for (int e = 0; e < 4; e++) acc[mf][of][e] = 0.f;

    int deg = 0;
    const int rq = w * 32 + gid;         // m-frag0 base row; m-frag1 at +16
    const int llr = tid >> 1;            // K/V row 0..63
    const int lgh = (tid & 1) * 2;       // group base: 0 or 2
    const int koff = ((gid >> 1) + ((gid & 1) << 2)) * 68 + tig * 16;
    const int qoff0 = rq * 68 + tig * 16;
    const int qoff1 = (rq + 8) * 68 + tig * 16;
    const int qoff2 = (rq + 16) * 68 + tig * 16;
    const int qoff3 = (rq + 24) * 68 + tig * 16;

    int stsb[2][4];
    #pragma unroll
    for (int g = 0; g < 2; g++)
        #pragma unroll
        for (int j = 0; j < 4; j++) {
            int c0 = (lgh + g) * 16 + j * 4;
            stsb[g][j] = llr * 68 + ((c0 >> 3) << 1) + ((c0 >> 2) & 1);
        }

    uint4 rk[2][4], rv[2][4];
    float rkb = 0.f;

    // prologue: tile 0 -> buffer 0
    #pragma unroll
    for (int g = 0; g < 2; g++)
        #pragma unroll
        for (int j = 0; j < 4; j++) {
            int c0 = (lgh + g) * 16 + j * 4;
            rk[g][j] = *(const uint4*)(Kg + (size_t)llr * HD + c0);
            rv[g][j] = *(const uint4*)(Vg + (size_t)llr * SS + c0);
        }
    if (tid < 64) rkb = v_mask[b * SS + tid] ? 0.f : -CMSK;
    {
        unsigned* Kb = KV;
        unsigned* Vb = KV + 64 * 68;
        #pragma unroll
        for (int g = 0; g < 2; g++)
            #pragma unroll
            for (int j = 0; j < 4; j++) {
                Kb[stsb[g][j]]      = rk[g][j].x;  Kb[stsb[g][j] + 16] = rk[g][j].y;
                Kb[stsb[g][j] + 32] = rk[g][j].z;  Kb[stsb[g][j] + 48] = rk[g][j].w;
                Vb[stsb[g][j]]      = rv[g][j].x;  Vb[stsb[g][j] + 16] = rv[g][j].y;
                Vb[stsb[g][j] + 32] = rv[g][j].z;  Vb[stsb[g][j] + 48] = rv[g][j].w;
            }
        if (tid < 64) kbb[tid] = rkb;
    }
    __syncthreads();

    for (int kt = 0; kt < NT; kt++) {
        if (kt > kt_hi && !deg) break;
        const int k0 = kt * 64;
        const int cur = kt & 1, nxt = cur ^ 1;
        const unsigned* Kp = KV + cur * (2 * 64 * 68);
        const unsigned* Vp = Kp + 64 * 68;
        const float* kb = kbb + cur * 64;
        const bool pf = (kt + 1 < NT);

        // ---- QK: both m-frags share each K fragment load ----
        float sc[2][8][4];
        #pragma unroll
        for (int mf = 0; mf < 2; mf++)
            #pragma unroll
            for (int nf = 0; nf < 8; nf++)
                #pragma unroll
                for (int e = 0; e < 4; e++) sc[mf][nf][e] = 0.f;

        #pragma unroll
        for (int j = 0; j < 4; j++) {
            uint4 a0 = *(const uint4*)&Qp[qoff0 + j * 4];
            uint4 a1 = *(const uint4*)&Qp[qoff1 + j * 4];
            uint4 a2 = *(const uint4*)&Qp[qoff2 + j * 4];
            uint4 a3 = *(const uint4*)&Qp[qoff3 + j * 4];
            unsigned Ae0[4] = {a0.x, a1.x, a0.y, a1.y};
            unsigned Ao0[4] = {a0.z, a1.z, a0.w, a1.w};
            unsigned Ae1[4] = {a2.x, a3.x, a2.y, a3.y};
            unsigned Ao1[4] = {a2.z, a3.z, a2.w, a3.w};
            #pragma unroll
            for (int nf = 0; nf < 8; nf++) {
                uint4 bv = *(const uint4*)&Kp[nf * 544 + koff + j * 4];
                unsigned Be[2] = {bv.x, bv.y};
                unsigned Bo[2] = {bv.z, bv.w};
                mma8(sc[0][nf], Ae0, Be);
                mma8(sc[0][nf], Ao0, Bo);
                mma8(sc[1][nf], Ae1, Be);
                mma8(sc[1][nf], Ao1, Bo);
            }
        }

        // ---- prefetch tile kt+1 (LDG overlapped by softmax + PV) ----
        if (pf) {
            const int nk0 = k0 + 64;
            #pragma unroll
            for (int g = 0; g < 2; g++)
                #pragma unroll
                for (int j = 0; j < 4; j++) {
                    int c0 = (lgh + g) * 16 + j * 4;
                    rk[g][j] = *(const uint4*)(Kg + (size_t)(nk0 + llr) * HD + c0);
                    rv[g][j] = *(const uint4*)(Vg + (size_t)llr * SS + nk0 + c0);
                }
            if (tid < 64) rkb = v_mask[b * SS + nk0 + tid] ? 0.f : -CMSK;
        }

        // ---- mask + online softmax; sc[mf][nf][2i+jj] <-> key nf*8+tig+4*jj ----
        float kb0[8], kb1[8];
        #pragma unroll
        for (int nf = 0; nf < 8; nf++) {
            kb0[nf] = kb[nf * 8 + tig];
            kb1[nf] = kb[nf * 8 + tig + 4];
        }
        #pragma unroll
        for (int mf = 0; mf < 2; mf++)
            #pragma unroll
            for (int i = 0; i < 2; i++) {
                int qg = q0 + rq + mf * 16 + 8 * i;
                float mx = NEG_INF;
                #pragma unroll
                for (int nf = 0; nf < 8; nf++) {
                    float s0 = sc[mf][nf][2 * i + 0] + kb0[nf];
                    float s1 = sc[mf][nf][2 * i + 1] + kb1[nf];
                    if (k0 + nf * 8 + tig > qg)     s0 -= CMSK;
                    if (k0 + nf * 8 + tig + 4 > qg) s1 -= CMSK;
                    sc[mf][nf][2 * i + 0] = s0;
                    sc[mf][nf][2 * i + 1] = s1;
                    mx = fmaxf(mx, fmaxf(s0, s1));
                }
                mx = fmaxf(mx, __shfl_xor_sync(0xffffffffu, mx, 1));
                mx = fmaxf(mx, __shfl_xor_sync(0xffffffffu, mx, 2));
                float nm = fmaxf(m[mf][i], mx);
                float rs = 0.f;
                #pragma unroll
                for (int nf = 0; nf < 8; nf++)
                    #pragma unroll
                    for (int jj = 0; jj < 2; jj++) {
                        float p = ex2(sc[mf][nf][2 * i + jj] - nm);
                        rs += p;
                        sc[mf][nf][2 * i + jj] = __uint_as_float(f2tf(p));
                    }
                rs += __shfl_xor_sync(0xffffffffu, rs, 1);
                rs += __shfl_xor_sync(0xffffffffu, rs, 2);
                float alpha = ex2(m[mf][i] - nm);
                l[mf][i] = l[mf][i] * alpha + rs;
                m[mf][i] = nm;
                #pragma unroll
                for (int of = 0; of < 8; of++) {
                    acc[mf][of][2 * i + 0] *= alpha;
                    acc[mf][of][2 * i + 1] *= alpha;
                }
            }

        // ---- PV: both m-frags share each V fragment load ----
        #pragma unroll
        for (int of = 0; of < 8; of++) {
            const unsigned* vb = &Vp[(of * 8 + gid) * 68 + tig * 16];
            uint4 ww[4];
            ww[0] = *(const uint4*)(vb);
            ww[1] = *(const uint4*)(vb + 4);
            ww[2] = *(const uint4*)(vb + 8);
            ww[3] = *(const uint4*)(vb + 12);
            #pragma unroll
            for (int nf = 0; nf < 8; nf++) {
                unsigned Bf[2];
                if ((nf & 1) == 0) { Bf[0] = ((const unsigned*)&ww[nf >> 1])[0];
                                     Bf[1] = ((const unsigned*)&ww[nf >> 1])[1]; }
                else               { Bf[0] = ((const unsigned*)&ww[nf >> 1])[2];
                                     Bf[1] = ((const unsigned*)&ww[nf >> 1])[3]; }
                #pragma unroll
                for (int mf = 0; mf < 2; mf++) {
                    unsigned Af[4] = {__float_as_uint(sc[mf][nf][0]), __float_as_uint(sc[mf][nf][2]),
                                      __float_as_uint(sc[mf][nf][1]), __float_as_uint(sc[mf][nf][3])};
                    mma8(acc[mf][of], Af, Bf);
                }
            }
        }

        // ---- STS prefetched tile into the other buffer ----
        if (pf) {
            unsigned* Kb = KV + nxt * (2 * 64 * 68);
            unsigned* Vb = Kb + 64 * 68;
            #pragma unroll
            for (int g = 0; g < 2; g++)
                #pragma unroll
                for (int j = 0; j < 4; j++) {
                    Kb[stsb[g][j]]      = rk[g][j].x;  Kb[stsb[g][j] + 16] = rk[g][j].y;
                    Kb[stsb[g][j] + 32] = rk[g][j].z;  Kb[stsb[g][j] + 48] = rk[g][j].w;
                    Vb[stsb[g][j]]      = rv[g][j].x;  Vb[stsb[g][j] + 16] = rv[g][j].y;
                    Vb[stsb[g][j] + 32] = rv[g][j].z;  Vb[stsb[g][j] + 48] = rv[g][j].w;
                }
            if (tid < 64) kbb[nxt * 64 + tid] = rkb;
        }

        // ---- single barrier per tile (doubles as degenerate-row vote) ----
        if (kt == kt_hi)
            deg = __syncthreads_or((m[0][0] < -1e10f) || (m[0][1] < -1e10f) ||
                                   (m[1][0] < -1e10f) || (m[1][1] < -1e10f));
        else
            __syncthreads();
    }

    // epilogue
    #pragma unroll
    for (int mf = 0; mf < 2; mf++)
        #pragma unroll
        for (int i = 0; i < 2; i++) {
            int qg = q0 + rq + mf * 16 + 8 * i;
            float qm = (float)q_mask[b * SS + qg];
            float f = qm / l[mf][i];
            #pragma unroll
            for (int of = 0; of < 8; of++) {
                float2 o = make_float2(acc[mf][of][2 * i + 0] * f, acc[mf][of][2 * i + 1] * f);
                *(float2*)(out + ((size_t)b * SS + qg) * ND + h * HD + of * 8 + tig * 2) = o;
            }
        }
}

// ---------------------------------------------------------------------------
extern "C" void kernel_launch(void* const* d_in, const int* in_sizes, int n_in,
                              void* d_out, int out_size)
{
    const float* q  = (const float*)d_in[0];
    const float* k  = (const float*)d_in[1];
    const float* v  = (const float*)d_in[2];
    const int* vmask = (const int*)d_in[3];
    const int* qmask = (const int*)d_in[4];
    const float* Wq = (const float*)d_in[5];
    const float* Wk = (const float*)d_in[6];
    const float* Wv = (const float*)d_in[7];
    float* out = (float*)d_out;

    const int smem_attn = (128 * 68 + 4 * 64 * 68 + 2 * 64) * 4;   // 104,960 B
    cudaFuncSetAttribute(attn_kernel, cudaFuncAttributeMaxDynamicSharedMemorySize, smem_attn);

    dim3 gp(ND / 128, (BB * SS) / 128, 3);   // (8, 32, 3)
    proj_kernel<<<gp, 128>>>(q, k, v, Wq, Wk, Wv);

    dim3 ga(SS / 128, BB * NH);              // (16, 32)
    attn_kernel<<<ga, 128, smem_attn>>>(vmask, qmask, out);
}